// round 7
// baseline (speedup 1.0000x reference)
#include <cuda_runtime.h>

#define DIM_B 4096
#define DIM_M 128
#define DIM_C 128
#define DIM_Q 256
#define VGB   16        // batches per block in vgemm (4 groups x 4)

// ---- scratch (static device globals: no allocation allowed) ----
__device__ float g_W [DIM_Q * DIM_Q];     // combined weight (256 x 256)
__device__ float g_xsum[DIM_B * DIM_Q];   // masked row sums (4 MB)
__device__ float g_v  [DIM_B * DIM_Q];    // per-batch query vectors (4 MB)
__device__ int   g_base[DIM_B];           // exclusive prefix sum of lens
__device__ int   g_sh_len;                // 0 = int32 seq_lengths, 1 = int64

typedef unsigned long long ull;

__device__ __forceinline__ ull pack2(float lo, float hi) {
    ull r; asm("mov.b64 %0, {%1, %2};" : "=l"(r) : "f"(lo), "f"(hi)); return r;
}
__device__ __forceinline__ void unpack2(ull v, float& lo, float& hi) {
    asm("mov.b64 {%0, %1}, %2;" : "=f"(lo), "=f"(hi) : "l"(v));
}
__device__ __forceinline__ ull fma2(ull a, ull b, ull c) {
    ull d; asm("fma.rn.f32x2 %0, %1, %2, %3;" : "=l"(d) : "l"(a), "l"(b), "l"(c)); return d;
}

// ---- K0: dtype detect + exclusive prefix scan of seq_lengths ----
__global__ void scan_kernel(const int* __restrict__ seq) {
    int sh = (seq[1] == 0) ? 1 : 0;
    if (threadIdx.x == 0) g_sh_len = sh;

    __shared__ int cs[1024], cs2[1024];
    int t = threadIdx.x;              // 1024 threads, 4 lens each
    int l[4]; int sum = 0;
#pragma unroll
    for (int i = 0; i < 4; i++) {
        l[i] = seq[(size_t)(4 * t + i) << sh];
        sum += l[i];
    }
    cs[t] = sum;
    __syncthreads();
    int* src = cs; int* dst = cs2;
    for (int off = 1; off < 1024; off <<= 1) {
        int v = src[t];
        if (t >= off) v += src[t - off];
        dst[t] = v;
        __syncthreads();
        int* tmp = src; src = dst; dst = tmp;
    }
    int run = (t > 0) ? src[t - 1] : 0;   // exclusive chunk base
#pragma unroll
    for (int i = 0; i < 4; i++) {
        g_base[4 * t + i] = run;
        run += l[i];
    }
}

// ---- K0a: fused W = (Wk^T Wc^T) @ proj. Block q computes row W[q][:]. ----
__global__ void wcomb_kernel(const float* __restrict__ Wk, const float* __restrict__ Wc,
                             const float* __restrict__ proj) {
    __shared__ float t1[DIM_M];       // T1[q][m] for this q
    int q = blockIdx.x;               // 0..255
    int t = threadIdx.x;              // 0..127
    float s = 0.f;
#pragma unroll 4
    for (int c = 0; c < DIM_C; c++)
        s = fmaf(Wk[c * DIM_Q + q], Wc[t * DIM_C + c], s);
    t1[t] = s;
    __syncthreads();
    float s0 = 0.f, s1 = 0.f;
#pragma unroll 4
    for (int m = 0; m < DIM_M; m++) {
        float a = t1[m];
        s0 = fmaf(a, proj[m * DIM_Q + t], s0);
        s1 = fmaf(a, proj[m * DIM_Q + 128 + t], s1);
    }
    g_W[q * DIM_Q + t]       = s0;
    g_W[q * DIM_Q + 128 + t] = s1;
}

// ---- K1: xsum[b][q] = sum_{m < len[b]} xss[b][m][q]  (block per batch) ----
__global__ void xsum_kernel(const float* __restrict__ xss, const int* __restrict__ seq) {
    int b   = blockIdx.x;
    int len = seq[(size_t)b << g_sh_len];
    int t   = threadIdx.x;           // 256 threads
    int q4  = t & 63;                // float4 column
    int mg  = t >> 6;                // row group 0..3
    const float4* base = (const float4*)xss + (size_t)b * (DIM_M * DIM_Q / 4);
    float4 acc = make_float4(0.f, 0.f, 0.f, 0.f);
#pragma unroll 4
    for (int m = mg; m < len; m += 4) {
        float4 v = base[m * (DIM_Q / 4) + q4];
        acc.x += v.x; acc.y += v.y; acc.z += v.z; acc.w += v.w;
    }
    __shared__ float4 red[4][64];
    red[mg][q4] = acc;
    __syncthreads();
    if (t < 64) {
        float4 a = red[0][t], c = red[1][t], d = red[2][t], e = red[3][t];
        float4 s;
        s.x = (a.x + c.x) + (d.x + e.x);
        s.y = (a.y + c.y) + (d.y + e.y);
        s.z = (a.z + c.z) + (d.z + e.z);
        s.w = (a.w + c.w) + (d.w + e.w);
        ((float4*)(g_xsum + (size_t)b * DIM_Q))[t] = s;
    }
}

// ---- K2: v = xsum @ W.  256 blocks x 256 threads, 16 batches/block. ----
// 4 groups of 64 threads; group g owns batches bb+4g..bb+4g+3 (2 ull pairs).
// Thread ct (0..63) owns W columns 4ct..4ct+3 via one LDG.128 per q.
// Per q per thread: 1 LDG.128 (W) + 1 broadcast LDS.128 (x) + 8 fma2.
__global__ void __launch_bounds__(256) vgemm_kernel() {
    __shared__ float xsT[DIM_Q * 20];      // [q][16 data + 4 pad], rows 16B-aligned

    int t  = threadIdx.x;                  // 0..255
    int bb = blockIdx.x * VGB;
    int g  = t >> 6;                       // group 0..3
    int ct = t & 63;                       // column quad

    // stage xsum transposed: xsT[q*20 + gb] = xsum[bb+gb][q]
    for (int idx = t; idx < VGB * DIM_Q; idx += 256) {
        int gb = idx >> 8, q = idx & 255;
        xsT[q * 20 + gb] = g_xsum[(size_t)(bb + gb) * DIM_Q + q];
    }
    __syncthreads();

    unsigned xaddr = (unsigned)__cvta_generic_to_shared(xsT) + (unsigned)g * 16u;
    const float4* Wg4 = (const float4*)g_W;   // row q = 64 float4

    ull acc00 = 0ull, acc01 = 0ull, acc02 = 0ull, acc03 = 0ull;  // pair 0, cols 0..3
    ull acc10 = 0ull, acc11 = 0ull, acc12 = 0ull, acc13 = 0ull;  // pair 1, cols 0..3

#pragma unroll 4
    for (int q = 0; q < DIM_Q; q++) {
        float4 wv = Wg4[q * 64 + ct];          // coalesced; L1/L2-resident
        ull x0, x1;                            // x[q][4g..4g+3], broadcast
        asm volatile("ld.shared.v2.u64 {%0,%1}, [%2];"
                     : "=l"(x0), "=l"(x1) : "r"(xaddr + (unsigned)q * 80u));
        ull w0 = pack2(wv.x, wv.x);
        ull w1 = pack2(wv.y, wv.y);
        ull w2 = pack2(wv.z, wv.z);
        ull w3 = pack2(wv.w, wv.w);
        acc00 = fma2(x0, w0, acc00);  acc10 = fma2(x1, w0, acc10);
        acc01 = fma2(x0, w1, acc01);  acc11 = fma2(x1, w1, acc11);
        acc02 = fma2(x0, w2, acc02);  acc12 = fma2(x1, w2, acc12);
        acc03 = fma2(x0, w3, acc03);  acc13 = fma2(x1, w3, acc13);
    }

    // write v for 4 batches, float4 per batch (coalesced across ct)
    int b0 = bb + 4 * g;
    float4 o;
    float lx, hx;
    unpack2(acc00, lx, hx); o.x = lx; float h0x = hx;
    unpack2(acc01, lx, hx); o.y = lx; float h0y = hx;
    unpack2(acc02, lx, hx); o.z = lx; float h0z = hx;
    unpack2(acc03, lx, hx); o.w = lx; float h0w = hx;
    ((float4*)(g_v + (size_t)(b0 + 0) * DIM_Q))[ct] = o;
    o.x = h0x; o.y = h0y; o.z = h0z; o.w = h0w;
    ((float4*)(g_v + (size_t)(b0 + 1) * DIM_Q))[ct] = o;
    unpack2(acc10, lx, hx); o.x = lx; h0x = hx;
    unpack2(acc11, lx, hx); o.y = lx; h0y = hx;
    unpack2(acc12, lx, hx); o.z = lx; h0z = hx;
    unpack2(acc13, lx, hx); o.w = lx; h0w = hx;
    ((float4*)(g_v + (size_t)(b0 + 2) * DIM_Q))[ct] = o;
    o.x = h0x; o.y = h0y; o.z = h0z; o.w = h0w;
    ((float4*)(g_v + (size_t)(b0 + 3) * DIM_Q))[ct] = o;
}

// ---- K3: y, block-per-batch, reversed order (L2 tail reuse), 2-row ILP ----
__global__ void y_kernel(const float* __restrict__ xss, const int* __restrict__ seq,
                         float* __restrict__ out) {
    int b    = (DIM_B - 1) - blockIdx.x;
    int len  = seq[(size_t)b << g_sh_len];
    int base = g_base[b];
    int t    = threadIdx.x;          // 256
    int w    = t >> 5, lane = t & 31;

    const float4* vr = (const float4*)(g_v + (size_t)b * DIM_Q);
    float4 v0 = vr[lane];
    float4 v1 = vr[lane + 32];

    const float4* xb = (const float4*)(xss + (size_t)b * DIM_M * DIM_Q);

    int m = w;
    for (; m + 8 < len; m += 16) {
        float4 a0 = xb[(size_t)m * 64 + lane];
        float4 a1 = xb[(size_t)m * 64 + 32 + lane];
        float4 c0 = xb[(size_t)(m + 8) * 64 + lane];
        float4 c1 = xb[(size_t)(m + 8) * 64 + 32 + lane];
        float s0 = 0.f, s1 = 0.f;
        s0 = fmaf(a0.x, v0.x, s0); s0 = fmaf(a0.y, v0.y, s0);
        s0 = fmaf(a0.z, v0.z, s0); s0 = fmaf(a0.w, v0.w, s0);
        s0 = fmaf(a1.x, v1.x, s0); s0 = fmaf(a1.y, v1.y, s0);
        s0 = fmaf(a1.z, v1.z, s0); s0 = fmaf(a1.w, v1.w, s0);
        s1 = fmaf(c0.x, v0.x, s1); s1 = fmaf(c0.y, v0.y, s1);
        s1 = fmaf(c0.z, v0.z, s1); s1 = fmaf(c0.w, v0.w, s1);
        s1 = fmaf(c1.x, v1.x, s1); s1 = fmaf(c1.y, v1.y, s1);
        s1 = fmaf(c1.z, v1.z, s1); s1 = fmaf(c1.w, v1.w, s1);
#pragma unroll
        for (int off = 16; off > 0; off >>= 1) {
            s0 += __shfl_xor_sync(0xffffffffu, s0, off);
            s1 += __shfl_xor_sync(0xffffffffu, s1, off);
        }
        if (lane == 0) {
            out[base + m]     = s0;
            out[base + m + 8] = s1;
        }
    }
    if (m < len) {
        float4 a0 = xb[(size_t)m * 64 + lane];
        float4 a1 = xb[(size_t)m * 64 + 32 + lane];
        float s0 = 0.f;
        s0 = fmaf(a0.x, v0.x, s0); s0 = fmaf(a0.y, v0.y, s0);
        s0 = fmaf(a0.z, v0.z, s0); s0 = fmaf(a0.w, v0.w, s0);
        s0 = fmaf(a1.x, v1.x, s0); s0 = fmaf(a1.y, v1.y, s0);
        s0 = fmaf(a1.z, v1.z, s0); s0 = fmaf(a1.w, v1.w, s0);
#pragma unroll
        for (int off = 16; off > 0; off >>= 1)
            s0 += __shfl_xor_sync(0xffffffffu, s0, off);
        if (lane == 0) out[base + m] = s0;
    }
}

extern "C" void kernel_launch(void* const* d_in, const int* in_sizes, int n_in,
                              void* d_out, int out_size) {
    const float* xss  = (const float*)d_in[0];
    const float* Wk   = (const float*)d_in[1];
    const float* Wc   = (const float*)d_in[2];
    const float* proj = (const float*)d_in[3];
    const int*   seq  = (const int*)d_in[4];
    float* out = (float*)d_out;

    scan_kernel<<<1, 1024>>>(seq);
    wcomb_kernel<<<DIM_Q, DIM_C>>>(Wk, Wc, proj);
    xsum_kernel<<<DIM_B, 256>>>(xss, seq);
    vgemm_kernel<<<DIM_B / VGB, 256>>>();
    y_kernel<<<DIM_B, 256>>>(xss, seq, out);
}

// round 9
// speedup vs baseline: 1.4257x; 1.4257x over previous
#include <cuda_runtime.h>

#define DIM_B 4096
#define DIM_M 128
#define DIM_C 128
#define DIM_Q 256
#define MT 64          // batch tile
#define NT 64          // column tile
#define KC 64          // k chunk
#define APAD 72        // floats per A smem row  (16B-aligned vector reads)
#define BPAD 68        // floats per B smem row

// ---- scratch (static device globals: no allocation allowed) ----
__device__ float g_W [DIM_Q * DIM_Q];     // combined weight (256 x 256)
__device__ float g_xsum[DIM_B * DIM_Q];   // masked row sums (4 MB)
__device__ float g_v  [DIM_B * DIM_Q];    // per-batch query vectors (4 MB)
__device__ int   g_base[DIM_B];           // exclusive prefix sum of lens
__device__ int   g_sh_len;                // 0 = int32 seq_lengths, 1 = int64

typedef unsigned long long ull;

__device__ __forceinline__ ull pack2(float lo, float hi) {
    ull r; asm("mov.b64 %0, {%1, %2};" : "=l"(r) : "f"(lo), "f"(hi)); return r;
}
__device__ __forceinline__ void unpack2(ull v, float& lo, float& hi) {
    asm("mov.b64 {%0, %1}, %2;" : "=f"(lo), "=f"(hi) : "l"(v));
}
__device__ __forceinline__ ull fma2(ull a, ull b, ull c) {
    ull d; asm("fma.rn.f32x2 %0, %1, %2, %3;" : "=l"(d) : "l"(a), "l"(b), "l"(c)); return d;
}

// ---- K0: dtype detect + exclusive prefix scan of seq_lengths ----
__global__ void scan_kernel(const int* __restrict__ seq) {
    int sh = (seq[1] == 0) ? 1 : 0;
    if (threadIdx.x == 0) g_sh_len = sh;

    __shared__ int cs[1024], cs2[1024];
    int t = threadIdx.x;              // 1024 threads, 4 lens each
    int l[4]; int sum = 0;
#pragma unroll
    for (int i = 0; i < 4; i++) {
        l[i] = seq[(size_t)(4 * t + i) << sh];
        sum += l[i];
    }
    cs[t] = sum;
    __syncthreads();
    int* src = cs; int* dst = cs2;
    for (int off = 1; off < 1024; off <<= 1) {
        int v = src[t];
        if (t >= off) v += src[t - off];
        dst[t] = v;
        __syncthreads();
        int* tmp = src; src = dst; dst = tmp;
    }
    int run = (t > 0) ? src[t - 1] : 0;   // exclusive chunk base
#pragma unroll
    for (int i = 0; i < 4; i++) {
        g_base[4 * t + i] = run;
        run += l[i];
    }
}

// ---- K0a: fused W = (Wk^T Wc^T) @ proj. Block q computes row W[q][:]. ----
__global__ void wcomb_kernel(const float* __restrict__ Wk, const float* __restrict__ Wc,
                             const float* __restrict__ proj) {
    __shared__ float t1[DIM_M];       // T1[q][m] for this q
    int q = blockIdx.x;               // 0..255
    int t = threadIdx.x;              // 0..127
    float s = 0.f;
#pragma unroll 4
    for (int c = 0; c < DIM_C; c++)
        s = fmaf(Wk[c * DIM_Q + q], Wc[t * DIM_C + c], s);
    t1[t] = s;
    __syncthreads();
    float s0 = 0.f, s1 = 0.f;
#pragma unroll 4
    for (int m = 0; m < DIM_M; m++) {
        float a = t1[m];
        s0 = fmaf(a, proj[m * DIM_Q + t], s0);
        s1 = fmaf(a, proj[m * DIM_Q + 128 + t], s1);
    }
    g_W[q * DIM_Q + t]       = s0;
    g_W[q * DIM_Q + 128 + t] = s1;
}

// ---- K1: xsum[b][q] = sum_{m < len[b]} xss[b][m][q]  (block per batch) ----
__global__ void xsum_kernel(const float* __restrict__ xss, const int* __restrict__ seq) {
    int b   = blockIdx.x;
    int len = seq[(size_t)b << g_sh_len];
    int t   = threadIdx.x;           // 256 threads
    int q4  = t & 63;                // float4 column
    int mg  = t >> 6;                // row group 0..3
    const float4* base = (const float4*)xss + (size_t)b * (DIM_M * DIM_Q / 4);
    float4 acc = make_float4(0.f, 0.f, 0.f, 0.f);
#pragma unroll 4
    for (int m = mg; m < len; m += 4) {
        float4 v = base[m * (DIM_Q / 4) + q4];
        acc.x += v.x; acc.y += v.y; acc.z += v.z; acc.w += v.w;
    }
    __shared__ float4 red[4][64];
    red[mg][q4] = acc;
    __syncthreads();
    if (t < 64) {
        float4 a = red[0][t], c = red[1][t], d = red[2][t], e = red[3][t];
        float4 s;
        s.x = (a.x + c.x) + (d.x + e.x);
        s.y = (a.y + c.y) + (d.y + e.y);
        s.z = (a.z + c.z) + (d.z + e.z);
        s.w = (a.w + c.w) + (d.w + e.w);
        ((float4*)(g_xsum + (size_t)b * DIM_Q))[t] = s;
    }
}

// ---- K2: v = xsum @ W as a smem-tiled GEMM.
// 256 blocks (64 M-tiles x 4 N-tiles) x 256 threads; thread = 4 batches x 4 cols.
// Inner loop is pure LDS + FFMA2; gmem only in the staging phases.
__global__ void __launch_bounds__(256) vgemm_kernel() {
    __shared__ float sA[KC * APAD];     // [k][m], 18.4 KB
    __shared__ float sB[KC * BPAD];     // [k][n], 17.4 KB

    int t  = threadIdx.x;               // 0..255
    int mt = (blockIdx.x >> 2) * MT;    // batch-tile base (adjacent blocks share it)
    int nt = (blockIdx.x & 3) * NT;     // column-tile base
    int iq = t >> 4;                    // batch quad 0..15 -> batches mt+4iq..+3
    int jq = t & 15;                    // col  quad 0..15 -> cols nt+4jq..+3

    unsigned aaddr0 = (unsigned)__cvta_generic_to_shared(sA) + 16u * (unsigned)iq;
    unsigned baddr0 = (unsigned)__cvta_generic_to_shared(sB) + 16u * (unsigned)jq;

    ull a00 = 0ull, a01 = 0ull, a02 = 0ull, a03 = 0ull;  // pair (4iq,4iq+1) x col 0..3
    ull a10 = 0ull, a11 = 0ull, a12 = 0ull, a13 = 0ull;  // pair (4iq+2,4iq+3)

    int sm = t >> 6;                    // A staging: row group 0..3
    int sk = t & 63;                    //            k within chunk
    int bk = t >> 4;                    // B staging: k row group (16 rows/pass)

    for (int kc = 0; kc < DIM_Q; kc += KC) {
        if (kc) __syncthreads();
        // stage A transposed: sA[k][m] = xsum[mt+m][kc+k]
#pragma unroll
        for (int p = 0; p < 16; p++) {
            int m = sm + 4 * p;
            sA[sk * APAD + m] = g_xsum[(size_t)(mt + m) * DIM_Q + kc + sk];
        }
        // stage B: sB[k][n] = W[kc+k][nt+n]
#pragma unroll
        for (int p = 0; p < 4; p++) {
            int k = bk + 16 * p;
            ((float4*)&sB[k * BPAD])[jq] =
                ((const float4*)&g_W[(kc + k) * DIM_Q + nt])[jq];
        }
        __syncthreads();

        unsigned aaddr = aaddr0, baddr = baddr0;
#pragma unroll 8
        for (int k = 0; k < KC; k++) {
            ull x0, x1;
            asm volatile("ld.shared.v2.u64 {%0,%1}, [%2];"
                         : "=l"(x0), "=l"(x1) : "r"(aaddr));
            float4 wv;
            asm volatile("ld.shared.v4.f32 {%0,%1,%2,%3}, [%4];"
                         : "=f"(wv.x), "=f"(wv.y), "=f"(wv.z), "=f"(wv.w) : "r"(baddr));
            ull w0 = pack2(wv.x, wv.x);
            ull w1 = pack2(wv.y, wv.y);
            ull w2 = pack2(wv.z, wv.z);
            ull w3 = pack2(wv.w, wv.w);
            a00 = fma2(x0, w0, a00);  a10 = fma2(x1, w0, a10);
            a01 = fma2(x0, w1, a01);  a11 = fma2(x1, w1, a11);
            a02 = fma2(x0, w2, a02);  a12 = fma2(x1, w2, a12);
            a03 = fma2(x0, w3, a03);  a13 = fma2(x1, w3, a13);
            aaddr += APAD * 4u;
            baddr += BPAD * 4u;
        }
    }

    // write 4x4 outputs: v[mt+4iq+r][nt+4jq..+3], float4 per batch (coalesced in jq)
    int b0 = mt + 4 * iq;
    int cq = (nt >> 2) + jq;            // float4 column index
    float4 o; float lo, hi, h0, h1, h2, h3;
    unpack2(a00, lo, hi); o.x = lo; h0 = hi;
    unpack2(a01, lo, hi); o.y = lo; h1 = hi;
    unpack2(a02, lo, hi); o.z = lo; h2 = hi;
    unpack2(a03, lo, hi); o.w = lo; h3 = hi;
    ((float4*)(g_v + (size_t)(b0 + 0) * DIM_Q))[cq] = o;
    o.x = h0; o.y = h1; o.z = h2; o.w = h3;
    ((float4*)(g_v + (size_t)(b0 + 1) * DIM_Q))[cq] = o;
    unpack2(a10, lo, hi); o.x = lo; h0 = hi;
    unpack2(a11, lo, hi); o.y = lo; h1 = hi;
    unpack2(a12, lo, hi); o.z = lo; h2 = hi;
    unpack2(a13, lo, hi); o.w = lo; h3 = hi;
    ((float4*)(g_v + (size_t)(b0 + 2) * DIM_Q))[cq] = o;
    o.x = h0; o.y = h1; o.z = h2; o.w = h3;
    ((float4*)(g_v + (size_t)(b0 + 3) * DIM_Q))[cq] = o;
}

// ---- K3: y, block-per-batch, reversed order (L2 tail reuse), 2-row ILP ----
__global__ void y_kernel(const float* __restrict__ xss, const int* __restrict__ seq,
                         float* __restrict__ out) {
    int b    = (DIM_B - 1) - blockIdx.x;
    int len  = seq[(size_t)b << g_sh_len];
    int base = g_base[b];
    int t    = threadIdx.x;          // 256
    int w    = t >> 5, lane = t & 31;

    const float4* vr = (const float4*)(g_v + (size_t)b * DIM_Q);
    float4 v0 = vr[lane];
    float4 v1 = vr[lane + 32];

    const float4* xb = (const float4*)(xss + (size_t)b * DIM_M * DIM_Q);

    int m = w;
    for (; m + 8 < len; m += 16) {
        float4 a0 = xb[(size_t)m * 64 + lane];
        float4 a1 = xb[(size_t)m * 64 + 32 + lane];
        float4 c0 = xb[(size_t)(m + 8) * 64 + lane];
        float4 c1 = xb[(size_t)(m + 8) * 64 + 32 + lane];
        float s0 = 0.f, s1 = 0.f;
        s0 = fmaf(a0.x, v0.x, s0); s0 = fmaf(a0.y, v0.y, s0);
        s0 = fmaf(a0.z, v0.z, s0); s0 = fmaf(a0.w, v0.w, s0);
        s0 = fmaf(a1.x, v1.x, s0); s0 = fmaf(a1.y, v1.y, s0);
        s0 = fmaf(a1.z, v1.z, s0); s0 = fmaf(a1.w, v1.w, s0);
        s1 = fmaf(c0.x, v0.x, s1); s1 = fmaf(c0.y, v0.y, s1);
        s1 = fmaf(c0.z, v0.z, s1); s1 = fmaf(c0.w, v0.w, s1);
        s1 = fmaf(c1.x, v1.x, s1); s1 = fmaf(c1.y, v1.y, s1);
        s1 = fmaf(c1.z, v1.z, s1); s1 = fmaf(c1.w, v1.w, s1);
#pragma unroll
        for (int off = 16; off > 0; off >>= 1) {
            s0 += __shfl_xor_sync(0xffffffffu, s0, off);
            s1 += __shfl_xor_sync(0xffffffffu, s1, off);
        }
        if (lane == 0) {
            out[base + m]     = s0;
            out[base + m + 8] = s1;
        }
    }
    if (m < len) {
        float4 a0 = xb[(size_t)m * 64 + lane];
        float4 a1 = xb[(size_t)m * 64 + 32 + lane];
        float s0 = 0.f;
        s0 = fmaf(a0.x, v0.x, s0); s0 = fmaf(a0.y, v0.y, s0);
        s0 = fmaf(a0.z, v0.z, s0); s0 = fmaf(a0.w, v0.w, s0);
        s0 = fmaf(a1.x, v1.x, s0); s0 = fmaf(a1.y, v1.y, s0);
        s0 = fmaf(a1.z, v1.z, s0); s0 = fmaf(a1.w, v1.w, s0);
#pragma unroll
        for (int off = 16; off > 0; off >>= 1)
            s0 += __shfl_xor_sync(0xffffffffu, s0, off);
        if (lane == 0) out[base + m] = s0;
    }
}

extern "C" void kernel_launch(void* const* d_in, const int* in_sizes, int n_in,
                              void* d_out, int out_size) {
    const float* xss  = (const float*)d_in[0];
    const float* Wk   = (const float*)d_in[1];
    const float* Wc   = (const float*)d_in[2];
    const float* proj = (const float*)d_in[3];
    const int*   seq  = (const int*)d_in[4];
    float* out = (float*)d_out;

    scan_kernel<<<1, 1024>>>(seq);
    wcomb_kernel<<<DIM_Q, DIM_C>>>(Wk, Wc, proj);
    xsum_kernel<<<DIM_B, 256>>>(xss, seq);
    vgemm_kernel<<<256, 256>>>();
    y_kernel<<<DIM_B, 256>>>(xss, seq, out);
}